// round 6
// baseline (speedup 1.0000x reference)
#include <cuda_runtime.h>
#include <cuda_bf16.h>

// Problem constants
#define QN      4        // n_codebooks
#define KCODES  512      // codes per codebook
#define DDIM    256      // vector dim (== C)
#define HH      1024
#define WW      4
#define BB      16
#define NROWS   65536    // B*W*H
#define TILE_H  16
#define ROWS    64       // rows per CTA (TILE_H * WW)
#define CTILE   64       // codes per smem tile
#define KK      128      // DDIM/2 (float2 pairs)
#define NCTA    1024     // BB * (HH/TILE_H)

#define IDX_OFF   (NROWS*DDIM)            // 16777216
#define LOSS_OFF  (IDX_OFF + NROWS*QN)    // 17039360

// ||c||^2 emulating XLA-GPU row-reduce: 32 strided partials (mul+add), shfl tree
__device__ float g_norms[QN*KCODES];
__device__ float g_loss_part[NCTA][QN];

struct SmemT {
    float2 xs2[KK][ROWS];   // residual, EXACT fp32, pair-interleaved
    float2 cs2[KK][CTILE];  // code tile (exact fp32)
    float  cn[CTILE];       // code norms for tile
    float  r2f[ROWS];       // ||r||^2 (XLA-GPU-order emulated) at stage start
    int    cand[2][ROWS];   // top-2 candidate indices per row
    float  dc[2][ROWS];     // rescored reference-style distances
    int    sidx[ROWS];
    float  rsum[ROWS];
};
#define SMEM_BYTES (sizeof(SmemT))

// Packed dual-fp32 FMA (B300 FFMA2) — 2x fp32 throughput vs scalar FFMA.
__device__ __forceinline__ void ffma2(float2 &d, const float2 &a, const float2 &b) {
    unsigned long long dd = *reinterpret_cast<const unsigned long long*>(&d);
    asm("fma.rn.f32x2 %0, %1, %2, %3;"
        : "=l"(dd)
        : "l"(*reinterpret_cast<const unsigned long long*>(&a)),
          "l"(*reinterpret_cast<const unsigned long long*>(&b)),
          "l"(dd));
    d = *reinterpret_cast<float2*>(&dd);
}

// insert candidate (sc,gi) into sorted best-2 list; ties keep lower index
__device__ __forceinline__ void upd2(float &b0, int &i0, float &b1, int &i1,
                                     float sc, int gi) {
    if (sc < b0 || (sc == b0 && gi < i0)) {
        b1 = b0; i1 = i0; b0 = sc; i0 = gi;
    } else if (sc < b1 || (sc == b1 && gi < i1)) {
        b1 = sc; i1 = gi;
    }
}

// ---------------- code norms: XLA-GPU row-reduce emulation ----------------
// One warp per code. Lane t: acc over k = t + 32*i (mul then add, no fma),
// then shfl_down tree at offsets 16,8,4,2,1. Lane 0 holds the result.
__global__ void rvq_norms_kernel(const float* __restrict__ cb) {
    int warp = (blockIdx.x * blockDim.x + threadIdx.x) >> 5;
    int lane = threadIdx.x & 31;
    if (warp >= QN * KCODES) return;
    const float* row = cb + (long)warp * DDIM;
    float s = 0.f;
    #pragma unroll
    for (int i = 0; i < 8; ++i) {
        float v = __ldg(&row[lane + 32 * i]);
        s = __fadd_rn(s, __fmul_rn(v, v));
    }
    #pragma unroll
    for (int off = 16; off >= 1; off >>= 1)
        s = __fadd_rn(s, __shfl_down_sync(0xffffffffu, s, off));
    if (lane == 0) g_norms[warp] = s;
}

// ---------------- main fused RVQ ----------------
__global__ __launch_bounds__(256, 1)
void rvq_main_kernel(const float* __restrict__ x, const float* __restrict__ cb,
                     float* __restrict__ out, int out_size) {
    extern __shared__ char smem_raw[];
    SmemT& S = *reinterpret_cast<SmemT*>(smem_raw);

    const int tid = threadIdx.x;
    const int tx = tid & 15;       // code group
    const int ty = tid >> 4;       // row group
    const int cta = blockIdx.x;
    const int b  = cta >> 6;
    const int h0 = (cta & 63) * TILE_H;

    // ---- load x tile into smem (coalesced: per c, 64 contiguous floats) ----
    {
        const float4* xsrc4 = reinterpret_cast<const float4*>(x);
        #pragma unroll
        for (int t = tid; t < DDIM * 16; t += 256) {
            int c = t >> 4;
            int f4c = t & 15;
            long idx4 = ((long)(b * DDIM + c)) * HH + h0 + f4c; // float4 index
            float4 v = __ldg(&xsrc4[idx4]);
            int kk = c >> 1;
            int hi = c & 1;
            int lr0 = f4c * 4;
            reinterpret_cast<float*>(&S.xs2[kk][lr0 + 0])[hi] = v.x;
            reinterpret_cast<float*>(&S.xs2[kk][lr0 + 1])[hi] = v.y;
            reinterpret_cast<float*>(&S.xs2[kk][lr0 + 2])[hi] = v.z;
            reinterpret_cast<float*>(&S.xs2[kk][lr0 + 3])[hi] = v.w;
        }
    }
    __syncthreads();

    const bool write_idx = (out_size >= IDX_OFF + NROWS*QN);

    // ---- 4 sequential quantization stages ----
    for (int q = 0; q < QN; ++q) {
        // ||r||^2 emulating XLA-GPU row-reduce: 32 strided partials (mul+add,
        // ascending i), then the shfl_down-16/8/4/2/1 tree order.
        if (tid < ROWS) {
            float p[32];
            #pragma unroll
            for (int t = 0; t < 32; ++t) {
                float s = 0.f;
                #pragma unroll
                for (int i = 0; i < 8; ++i) {
                    int k = t + 32 * i;
                    float v = reinterpret_cast<const float*>(&S.xs2[k >> 1][tid])[k & 1];
                    s = __fadd_rn(s, __fmul_rn(v, v));
                }
                p[t] = s;
            }
            #pragma unroll
            for (int off = 16; off >= 1; off >>= 1)
                #pragma unroll
                for (int t = 0; t < 16; ++t)
                    if (t < off) p[t] = __fadd_rn(p[t], p[t + off]);
            S.r2f[tid] = p[0];
        }

        float best0[4], best1[4];
        int   idx0[4],  idx1[4];
        #pragma unroll
        for (int i = 0; i < 4; ++i) {
            best0[i] = 3.4e38f; best1[i] = 3.4e38f;
            idx0[i] = 0x7fffffff; idx1[i] = 0x7fffffff;
        }

        for (int ct = 0; ct < KCODES / CTILE; ++ct) {
            __syncthreads();  // previous tile compute done / cs2 free; r2f done (ct==0)
            // load 64 codes x 256 dims into cs2 (pair-interleaved)
            const float4* cbsrc = reinterpret_cast<const float4*>(
                cb + ((long)(q * KCODES + ct * CTILE)) * DDIM);
            #pragma unroll
            for (int t = tid; t < CTILE * 64; t += 256) {
                int j  = t >> 6;
                int f4 = t & 63;
                float4 v = __ldg(&cbsrc[j * 64 + f4]);
                int kk = f4 * 2;
                S.cs2[kk][j]     = make_float2(v.x, v.y);
                S.cs2[kk + 1][j] = make_float2(v.z, v.w);
            }
            if (tid < CTILE) S.cn[tid] = g_norms[q * KCODES + ct * CTILE + tid];
            __syncthreads();

            // 4x4 register-blocked fp32 dot products, FFMA2 inner loop (approx scan)
            float2 acc[4][4];
            #pragma unroll
            for (int i = 0; i < 4; ++i)
                #pragma unroll
                for (int j = 0; j < 4; ++j) acc[i][j] = make_float2(0.f, 0.f);

            #pragma unroll 8
            for (int kk = 0; kk < KK; ++kk) {
                float4 ra = *reinterpret_cast<const float4*>(&S.xs2[kk][ty * 4]);
                float4 rb = *reinterpret_cast<const float4*>(&S.xs2[kk][ty * 4 + 2]);
                float4 ca = *reinterpret_cast<const float4*>(&S.cs2[kk][tx * 4]);
                float4 cc = *reinterpret_cast<const float4*>(&S.cs2[kk][tx * 4 + 2]);
                float2 rv[4] = { make_float2(ra.x, ra.y), make_float2(ra.z, ra.w),
                                 make_float2(rb.x, rb.y), make_float2(rb.z, rb.w) };
                float2 cv[4] = { make_float2(ca.x, ca.y), make_float2(ca.z, ca.w),
                                 make_float2(cc.x, cc.y), make_float2(cc.z, cc.w) };
                #pragma unroll
                for (int i = 0; i < 4; ++i)
                    #pragma unroll
                    for (int j = 0; j < 4; ++j)
                        ffma2(acc[i][j], rv[i], cv[j]);
            }
            // approximate scores for candidate SELECTION; keep best-2 per row
            #pragma unroll
            for (int j = 0; j < 4; ++j) {
                float n2 = S.cn[tx * 4 + j];
                int gidx = ct * CTILE + tx * 4 + j;
                #pragma unroll
                for (int i = 0; i < 4; ++i) {
                    float dot = acc[i][j].x + acc[i][j].y;
                    float sc = fmaf(-2.f, dot, n2);
                    upd2(best0[i], idx0[i], best1[i], idx1[i], sc, gidx);
                }
            }
        }

        // merge best-2 lists across the 16 tx lanes sharing each row
        #pragma unroll
        for (int i = 0; i < 4; ++i) {
            #pragma unroll
            for (int off = 8; off; off >>= 1) {
                float ob0 = __shfl_xor_sync(0xffffffffu, best0[i], off);
                int   oi0 = __shfl_xor_sync(0xffffffffu, idx0[i],  off);
                float ob1 = __shfl_xor_sync(0xffffffffu, best1[i], off);
                int   oi1 = __shfl_xor_sync(0xffffffffu, idx1[i],  off);
                upd2(best0[i], idx0[i], best1[i], idx1[i], ob0, oi0);
                upd2(best0[i], idx0[i], best1[i], idx1[i], ob1, oi1);
            }
        }
        if (tx == 0) {
            #pragma unroll
            for (int i = 0; i < 4; ++i) {
                S.cand[0][ty * 4 + i] = idx0[i];
                S.cand[1][ty * 4 + i] = idx1[i];
            }
        }
        __syncthreads();

        // ---- rescore top-2 emulating the reference (cuBLAS SGEMM) arithmetic ----
        // dot: serial ascending-k fp32 FMA (one accumulator per output element)
        // d  : fadd_rn( fsub_rn(r2, fmul_rn(2, dot)), c2 )
        if (tid < 2 * ROWS) {
            int row = tid >> 1;
            int c   = tid & 1;
            int idx = S.cand[c][row];
            const float2* crow = reinterpret_cast<const float2*>(
                cb + ((long)(q * KCODES + idx)) * DDIM);
            float acc = 0.f;
            #pragma unroll 8
            for (int kk = 0; kk < KK; ++kk) {
                float2 r  = S.xs2[kk][row];
                float2 cv = __ldg(&crow[kk]);
                acc = fmaf(r.x, cv.x, acc);
                acc = fmaf(r.y, cv.y, acc);
            }
            float t = __fsub_rn(S.r2f[row], __fmul_rn(2.f, acc));
            S.dc[c][row] = __fadd_rn(t, g_norms[q * KCODES + idx]);
        }
        __syncthreads();
        if (tid < ROWS) {
            float d0 = S.dc[0][tid], d1 = S.dc[1][tid];
            int   i0 = S.cand[0][tid], i1 = S.cand[1][tid];
            int win = (d1 < d0 || (d1 == d0 && i1 < i0)) ? i1 : i0;
            S.sidx[tid] = win;
        }
        __syncthreads();  // sidx visible; all xs2 reads done before mutation

        // residual update: r -= chosen code (4 threads per row, 64 dims each)
        {
            int lr = tid & 63;
            int ks = tid >> 6;
            int idx = S.sidx[lr];
            const float4* crow = reinterpret_cast<const float4*>(
                cb + ((long)(q * KCODES + idx)) * DDIM);
            #pragma unroll
            for (int f4 = ks * 16; f4 < ks * 16 + 16; ++f4) {
                float4 v = __ldg(&crow[f4]);
                int kk = f4 * 2;
                float2 a = S.xs2[kk][lr];     a.x -= v.x; a.y -= v.y; S.xs2[kk][lr] = a;
                float2 c2 = S.xs2[kk + 1][lr]; c2.x -= v.z; c2.y -= v.w; S.xs2[kk + 1][lr] = c2;
            }
        }

        // indices output (as float)
        if (write_idx && tid < ROWS) {
            int w = tid & 3, hh = tid >> 2;
            long n = ((long)(b * WW + w)) * HH + h0 + hh;
            out[IDX_OFF + n * QN + q] = (float)S.sidx[tid];
        }
        __syncthreads();  // residual update complete

        // loss: elementwise sum ||r_{q+1}||^2 (deterministic order)
        if (tid < ROWS) {
            float s = 0.f;
            #pragma unroll 8
            for (int kk = 0; kk < KK; ++kk) {
                float2 v = S.xs2[kk][tid];
                s = fmaf(v.x, v.x, s);
                s = fmaf(v.y, v.y, s);
            }
            S.rsum[tid] = s;
        }
        __syncthreads();
        if (tid == 0) {
            float s = 0.f;
            #pragma unroll
            for (int i = 0; i < ROWS; ++i) s += S.rsum[i];
            g_loss_part[cta][q] = s;
        }
    }
    __syncthreads();

    // ---- quantized_out = x - residual_final (exact fp32) ----
    {
        int lr = tid & 63;
        int ks = tid >> 6;
        int w = lr & 3, hh = lr >> 2;
        long n = ((long)(b * WW + w)) * HH + h0 + hh;
        float4* orow = reinterpret_cast<float4*>(out + n * DDIM);
        long cbase = (((long)b * DDIM) * HH + (h0 + hh)) * WW + w;  // offset at c=0
        #pragma unroll
        for (int f4 = ks * 16; f4 < ks * 16 + 16; ++f4) {
            int c0 = f4 * 4;
            float x0 = __ldg(&x[cbase + (long)(c0 + 0) * (HH * WW)]);
            float x1 = __ldg(&x[cbase + (long)(c0 + 1) * (HH * WW)]);
            float x2 = __ldg(&x[cbase + (long)(c0 + 2) * (HH * WW)]);
            float x3 = __ldg(&x[cbase + (long)(c0 + 3) * (HH * WW)]);
            float2 r0 = S.xs2[f4 * 2][lr];
            float2 r1 = S.xs2[f4 * 2 + 1][lr];
            float4 o;
            o.x = x0 - r0.x; o.y = x1 - r0.y;
            o.z = x2 - r1.x; o.w = x3 - r1.y;
            orow[f4] = o;
        }
    }
}

// ---------------- loss finalize (deterministic fixed-order sum) ----------------
__global__ void rvq_finish_kernel(float* __restrict__ out, int out_size) {
    if (out_size < LOSS_OFF + QN) return;
    int q = threadIdx.x >> 5;
    int lane = threadIdx.x & 31;
    if (q >= QN) return;
    float s = 0.f;
    for (int i = lane; i < NCTA; i += 32) s += g_loss_part[i][q];
    #pragma unroll
    for (int off = 16; off; off >>= 1) s += __shfl_xor_sync(0xffffffffu, s, off);
    if (lane == 0) out[LOSS_OFF + q] = s / (float)(NROWS * DDIM);
}

extern "C" void kernel_launch(void* const* d_in, const int* in_sizes, int n_in,
                              void* d_out, int out_size) {
    const float* x  = (const float*)d_in[0];   // encoded_x [16,256,1024,4]
    const float* cb = (const float*)d_in[1];   // codebooks [4,512,256]
    float* out = (float*)d_out;

    cudaFuncSetAttribute(rvq_main_kernel,
                         cudaFuncAttributeMaxDynamicSharedMemorySize,
                         (int)SMEM_BYTES);

    rvq_norms_kernel<<<(QN*KCODES*32 + 255)/256, 256>>>(cb);
    rvq_main_kernel<<<NCTA, 256, SMEM_BYTES>>>(x, cb, out, out_size);
    rvq_finish_kernel<<<1, 128>>>(out, out_size);
}